// round 4
// baseline (speedup 1.0000x reference)
#include <cuda_runtime.h>

// GRU scan (SEQ=8192, NIN=NHID=1024), single persistent kernel.
//
//   128 CTAs x 512 threads (1 CTA/SM, all co-resident: 128 <= 148 SMs).
//   CTA c owns hidden units j = 8c..8c+7. Output j is computed by warp pair
//   (2i, 2i+1); each warp covers half of k (512 values) as 8 f32x2 pairs
//   per lane: k = half*512 + 2*lane + 64*p.
//
//   All weights in registers, packed f32x2 (48 x b64 per lane: W_ih + W_hh,
//   3 gates). Per step:
//     - input-part fma.rn.f32x2 from x_t (SMEM, double buffered) — overlaps
//       the inter-CTA barrier wait
//     - chip barrier: monotonic u64 counter, red.release arrive +
//       ld.acquire poll by tid0 (replay-safe: each launch advances the
//       counter by 128*8193, a multiple of 128)
//     - stage h_{t-1} = ys[t-1] into SMEM, recurrent-part fma.rn.f32x2
//     - f32x2 collapse, warp butterfly, pair combine via named barrier,
//       MUFU-based gate math on one lane, store ys[t] (both output copies)
//     - __syncthreads + red.release arrive

#define TT      8192
#define HH      1024
#define NCTA    128
#define OPC     8
#define THREADS 512
#define NP      8

typedef unsigned long long u64;

__device__ u64 g_count;    // zero-init; monotonic across graph replays

__device__ __forceinline__ u64 ld_acq(const u64* p) {
    u64 v;
    asm volatile("ld.acquire.gpu.global.b64 %0, [%1];" : "=l"(v) : "l"(p) : "memory");
    return v;
}
__device__ __forceinline__ u64 atom_add_rel(u64* p, u64 v) {
    u64 old;
    asm volatile("atom.release.gpu.global.add.u64 %0, [%1], %2;"
                 : "=l"(old) : "l"(p), "l"(v) : "memory");
    return old;
}
__device__ __forceinline__ void red_add_rel(u64* p, u64 v) {
    asm volatile("red.release.gpu.global.add.u64 [%0], %1;"
                 :: "l"(p), "l"(v) : "memory");
}

#define FMA2(d, a, b, c) \
    asm("fma.rn.f32x2 %0, %1, %2, %3;" : "=l"(d) : "l"(a), "l"(b), "l"(c))

__device__ __forceinline__ float hsum2(u64 v) {
    float2 f = *reinterpret_cast<float2*>(&v);
    return f.x + f.y;
}

// MUFU-based, NaN-safe activations (rel err ~1e-6, well under 1e-3 tol).
__device__ __forceinline__ float fast_sigmoid(float x) {
    return __frcp_rn(1.0f + __expf(-x));            // x=+-inf safe
}
__device__ __forceinline__ float fast_tanh(float x) {
    // tanh(x) = 1 - 2/(1 + e^{2x});  e^{2x}->inf => 1, ->0 => -1. No NaN.
    return 1.0f - 2.0f * __frcp_rn(1.0f + __expf(2.0f * x));
}

__global__ void __launch_bounds__(THREADS, 1)
gru_scan_kernel(const float* __restrict__ xs,
                const float* __restrict__ w_ih,
                const float* __restrict__ w_hh,
                const float* __restrict__ b,
                const float* __restrict__ bn,
                float* __restrict__ out,     // ys copy 1: [TT][HH]
                float* __restrict__ out2)    // ys copy 2 (may alias copy 1)
{
    __shared__ __align__(16) float sx[2][HH];   // x staging, double buffered
    __shared__ __align__(16) float sh[HH];      // h_{t-1} staging
    __shared__ float s_red[OPC][4];             // partner-warp partials
    __shared__ u64   s_base;

    const int tid  = threadIdx.x;
    const int w    = tid >> 5;
    const int lane = tid & 31;
    const int i    = w >> 1;              // output within CTA, 0..7
    const int half = w & 1;               // k-half
    const int j    = blockIdx.x * OPC + i;
    const int kp   = half * 256 + lane;   // u64 pair index; k = 2*(kp+32p)

    // ---- one-time: weights into registers, packed f32x2 ----
    u64 whr[NP], whz[NP], whg[NP];
    u64 wir[NP], wiz[NP], wig[NP];
#pragma unroll
    for (int p = 0; p < NP; p++) {
        size_t e = (size_t)2 * (kp + 32 * p);
        whr[p] = *reinterpret_cast<const u64*>(w_hh + (size_t)(j         ) * HH + e);
        whz[p] = *reinterpret_cast<const u64*>(w_hh + (size_t)(j +     HH) * HH + e);
        whg[p] = *reinterpret_cast<const u64*>(w_hh + (size_t)(j + 2 * HH) * HH + e);
        wir[p] = *reinterpret_cast<const u64*>(w_ih + (size_t)(j         ) * HH + e);
        wiz[p] = *reinterpret_cast<const u64*>(w_ih + (size_t)(j +     HH) * HH + e);
        wig[p] = *reinterpret_cast<const u64*>(w_ih + (size_t)(j + 2 * HH) * HH + e);
    }
    const float br  = b[j];
    const float bz  = b[j + HH];
    const float bg  = b[j + 2 * HH];
    const float bnj = bn[j];
    float hprev = 0.0f;

    // running pointers (avoid per-step IMAD on the serial path)
    const float* xptr = xs + HH + 2 * tid;        // x_{t+1} prefetch source
    const float* hptr = out - HH + 2 * tid;       // h_{t-1} = ys[t-1] source

    // stage x_0
    {
        float2 x0 = *reinterpret_cast<const float2*>(xs + 2 * tid);
        *reinterpret_cast<float2*>(&sx[0][2 * tid]) = x0;
    }

    // ---- per-launch counter base (monotonic => graph-replay-safe) ----
    if (tid == 0) {
        u64 old = atom_add_rel(&g_count, 1ULL);
        s_base = (old & ~(u64)(NCTA - 1)) + (u64)NCTA;
    }
    __syncthreads();
    u64 tgt = s_base;    // target for step 0; += NCTA per step

    for (int t = 0; t < TT; t++) {
        // prefetch x_{t+1} (hidden under compute + barrier wait)
        float2 xpre = (t + 1 < TT)
            ? *reinterpret_cast<const float2*>(xptr)
            : make_float2(0.0f, 0.0f);

        // ---- input part (independent of h_{t-1}) ----
        const u64* sx64 = reinterpret_cast<const u64*>(sx[t & 1]);
        u64 ar2 = 0, az2 = 0, aig2 = 0, ahg2 = 0;
#pragma unroll
        for (int p = 0; p < NP; p++) {
            u64 x2 = sx64[kp + 32 * p];
            FMA2(ar2,  wir[p], x2, ar2);
            FMA2(az2,  wiz[p], x2, az2);
            FMA2(aig2, wig[p], x2, aig2);
        }

        // ---- chip barrier: all CTAs finished step t-1 ----
        if (tid == 0) {
            while (ld_acq(&g_count) < tgt) { }
        }
        __syncthreads();   // tid0's acquire + bar => peer h-writes visible

        // ---- recurrent part from h_{t-1} = ys[t-1], staged via SMEM ----
        if (t > 0) {
            float2 hv = *reinterpret_cast<const float2*>(hptr);
            *reinterpret_cast<float2*>(&sh[2 * tid]) = hv;
            __syncthreads();

            const u64* sh64 = reinterpret_cast<const u64*>(sh);
#pragma unroll
            for (int p = 0; p < NP; p++) {
                u64 h2 = sh64[kp + 32 * p];
                FMA2(ar2,  whr[p], h2, ar2);
                FMA2(az2,  whz[p], h2, az2);
                FMA2(ahg2, whg[p], h2, ahg2);
            }
        }

        // ---- collapse f32x2 -> scalar, warp butterfly ----
        float ar  = hsum2(ar2);
        float az  = hsum2(az2);
        float aig = hsum2(aig2);
        float ahg = hsum2(ahg2);
#pragma unroll
        for (int off = 16; off > 0; off >>= 1) {
            ar  += __shfl_xor_sync(0xffffffffu, ar,  off);
            az  += __shfl_xor_sync(0xffffffffu, az,  off);
            aig += __shfl_xor_sync(0xffffffffu, aig, off);
            ahg += __shfl_xor_sync(0xffffffffu, ahg, off);
        }

        // ---- combine the two k-halves of this output ----
        if (half == 1 && lane == 0) {
            s_red[i][0] = ar;
            s_red[i][1] = az;
            s_red[i][2] = aig;
            s_red[i][3] = ahg;
        }
        asm volatile("bar.sync %0, 64;" :: "r"(i + 1) : "memory");

        if (half == 0 && lane == 0) {
            float tr  = ar  + s_red[i][0] + br;
            float tz  = az  + s_red[i][1] + bz;
            float tig = aig + s_red[i][2] + bg;
            float thg = ahg + s_red[i][3] + bnj;

            float r  = fast_sigmoid(tr);
            float z  = fast_sigmoid(tz);
            float g  = fast_tanh(fmaf(r, thg, tig));
            float hn = fmaf(z, hprev - g, g);      // (1-z)g + z h
            hprev = hn;

            size_t o = (size_t)t * HH + j;
            out[o]  = hn;
            out2[o] = hn;
        }

        // stage x_{t+1}
        *reinterpret_cast<float2*>(&sx[(t + 1) & 1][2 * tid]) = xpre;

        __syncthreads();            // order h stores + x staging before arrive
        if (tid == 0) red_add_rel(&g_count, 1ULL);
        tgt  += NCTA;
        xptr += HH;
        hptr += HH;
    }
}

extern "C" void kernel_launch(void* const* d_in, const int* in_sizes, int n_in,
                              void* d_out, int out_size) {
    const float* xs   = (const float*)d_in[0];   // [8192,1024]
    const float* w_ih = (const float*)d_in[1];   // [3072,1024]
    const float* w_hh = (const float*)d_in[2];   // [3072,1024]
    const float* b    = (const float*)d_in[3];   // [3072]
    const float* bn   = (const float*)d_in[4];   // [1024]
    float* out = (float*)d_out;

    const size_t TH = (size_t)TT * HH;
    // Reference returns (ys, ys): duplicate if the out buffer holds both.
    float* out2 = ((size_t)out_size >= 2 * TH) ? (out + TH) : out;

    gru_scan_kernel<<<NCTA, THREADS>>>(xs, w_ih, w_hh, b, bn, out, out2);
}